// round 4
// baseline (speedup 1.0000x reference)
#include <cuda_runtime.h>
#include <cuda_bf16.h>
#include <cstdint>

// ContinuousEmbedding: out[b,f,:] = sum_k weight[k,:] / (|idx(x[b,f]) - k| + 1)
// Collapses to a 64x64 lookup table T (16 KB) indexed by bucket index.
//
// R4: TMA bulk stores. Blocks stage 128-row (32 KB) output tiles in shared
// memory (LDS table -> STS staging, conflict-free), then one thread issues
// cp.async.bulk shared->global (UTMASTG), double-buffered. This removes the
// per-warp STG issue path that capped R2/R3 at ~50% of the LTS store cap.

#define NUM_BINS 63
#define KDIM 64          // NUM_BINS + 1
#define EMB_DIM 64
#define TILE_ROWS 128
#define TILE_F4   (TILE_ROWS * (EMB_DIM / 4))   // 2048 float4 = 32 KB
#define TILE_BYTES (TILE_F4 * 16)

__device__ float g_table[KDIM * EMB_DIM];   // scratch (allocation-free rule)

__device__ __forceinline__ uint32_t smem_u32(const void* p) {
    return (uint32_t)__cvta_generic_to_shared(p);
}

// ---------------------------------------------------------------------------
// Kernel 1: T[i][d] = sum_k weight[k][d] * (1/(|i-k|+1)).  <<<16, 256>>>
// ---------------------------------------------------------------------------
__global__ void __launch_bounds__(256)
build_table_kernel(const float* __restrict__ weight) {
    __shared__ float sw[KDIM * EMB_DIM];          // 16 KB
    float4* sw4 = reinterpret_cast<float4*>(sw);
    const float4* w4 = reinterpret_cast<const float4*>(weight);
#pragma unroll
    for (int i = threadIdx.x; i < KDIM * EMB_DIM / 4; i += 256)
        sw4[i] = w4[i];
    __syncthreads();

    const int r = blockIdx.x * 4 + (threadIdx.x >> 6);  // table row 0..63
    const int d = threadIdx.x & 63;                     // emb dim 0..63
    float acc = 0.0f;
#pragma unroll
    for (int k = 0; k < KDIM; ++k) {
        int diff = r - k; if (diff < 0) diff = -diff;
        acc = fmaf(sw[k * EMB_DIM + d], 1.0f / (float)(diff + 1), acc);
    }
    g_table[r * EMB_DIM + d] = acc;

#if __CUDA_ARCH__ >= 900
    cudaTriggerProgrammaticLaunchCompletion();
#endif
}

// ---------------------------------------------------------------------------
// Kernel 2: TMA-store embed. 296 blocks x 256 threads, 2 blocks/SM (80 KB
// dynamic smem each). Grid-stride over 128-row tiles.
// Per tile: 8 warps x 16 rows. Lane<16 computes the bucket index of one row;
// then 8 unrolled {shfl, LDS.128 table, STS.128 staging} steps fill the tile;
// one thread issues a 32 KB cp.async.bulk store. Double-buffered.
// ---------------------------------------------------------------------------
extern __shared__ float4 smem_dyn[];   // [0,1024): table  [1024, 1024+2*2048): staging

__global__ void __launch_bounds__(256)
embed_kernel(const float* __restrict__ x,
             const float* __restrict__ low,   // [64]; low[0]=-inf, bins=low[1..]
             float* __restrict__ out,
             int n_rows)
{
    float4* sT    = smem_dyn;            // 1024 float4 (16 KB)
    float4* stage = smem_dyn + 1024;     // 2 x 2048 float4 (2 x 32 KB)

    const int tid  = threadIdx.x;
    const int lane = tid & 31;
    const int warp = tid >> 5;
    const int half = lane >> 4;          // row-within-pair
    const int part = lane & 15;          // float4 slot within a 64-float row

#if __CUDA_ARCH__ >= 900
    cudaGridDependencySynchronize();     // g_table must be ready
#endif

    // Load table into shared (L2-broadcast across blocks)
    const float4* gT4 = reinterpret_cast<const float4*>(g_table);
#pragma unroll
    for (int i = tid; i < 1024; i += 256)
        sT[i] = __ldg(gT4 + i);
    __syncthreads();

    const int n_tiles = n_rows / TILE_ROWS;
    int buf = 0;

    for (int tile = blockIdx.x; tile < n_tiles; tile += gridDim.x) {
        // --- bucket indices: lane<16 handles row tile*128 + warp*16 + lane ---
        int g = 0;
        if (lane < 16) {
            const float xv = __ldg(x + tile * TILE_ROWS + warp * 16 + lane);
            // index = #{ j : bins[j] < x }: arithmetic guess + EXACT fixup
            g = (int)floorf((xv + 3.1f) * 10.0f) + 1;
            g = max(0, min(NUM_BINS, g));
            while (g > 0 && !(xv > __ldg(low + g))) --g;
            while (g < NUM_BINS && (xv > __ldg(low + g + 1))) ++g;
        }

        // --- wait until this buffer's previous TMA store has read it out ---
        if (tid == 0)
            asm volatile("cp.async.bulk.wait_group.read 1;" ::: "memory");
        __syncthreads();

        // --- fill staging: 8 x (shfl -> LDS.128 -> STS.128), conflict-free ---
        float4* dst = stage + buf * TILE_F4 + warp * 16 * 16;   // warp's 16 rows
#pragma unroll
        for (int j = 0; j < 8; ++j) {
            const int idx = __shfl_sync(0xffffffffu, g, 2 * j + half);
            const float4 v = sT[(idx << 4) + part];
            dst[(2 * j + half) * 16 + part] = v;
        }
        __syncthreads();

        // --- one thread issues the 32 KB bulk store ---
        if (tid == 0) {
            asm volatile("fence.proxy.async.shared::cta;" ::: "memory");
            const float* gdst = out + (size_t)tile * TILE_ROWS * EMB_DIM;
            asm volatile(
                "cp.async.bulk.global.shared::cta.bulk_group [%0], [%1], %2;"
                :: "l"(gdst), "r"(smem_u32(stage + buf * TILE_F4)),
                   "r"((uint32_t)TILE_BYTES)
                : "memory");
            asm volatile("cp.async.bulk.commit_group;" ::: "memory");
        }
        buf ^= 1;
    }

    // --- remainder rows (n_rows not multiple of 128): plain stores, block 0 ---
    const int rem_base = n_tiles * TILE_ROWS;
    if (blockIdx.x == 0 && rem_base < n_rows) {
        for (int r = rem_base + warp; r < n_rows; r += 8) {
            int gg = 0;
            if (lane == 0) {
                const float xv = __ldg(x + r);
                gg = (int)floorf((xv + 3.1f) * 10.0f) + 1;
                gg = max(0, min(NUM_BINS, gg));
                while (gg > 0 && !(xv > __ldg(low + gg))) --gg;
                while (gg < NUM_BINS && (xv > __ldg(low + gg + 1))) ++gg;
            }
            gg = __shfl_sync(0xffffffffu, gg, 0);
            if (lane < 16)
                reinterpret_cast<float4*>(out)[(size_t)r * 16 + lane] =
                    sT[(gg << 4) + lane];
        }
    }

    // ensure all bulk stores are fully complete before grid end
    if (tid == 0)
        asm volatile("cp.async.bulk.wait_group 0;" ::: "memory");
}

extern "C" void kernel_launch(void* const* d_in, const int* in_sizes, int n_in,
                              void* d_out, int out_size) {
    const float* x      = (const float*)d_in[0];   // [B*F]
    const float* low    = (const float*)d_in[1];   // [64]
    // d_in[2] = high [64] (redundant with low for the bucket computation)
    const float* weight = (const float*)d_in[3];   // [64*64]

    float* out = (float*)d_out;
    const int n_rows = out_size / EMB_DIM;         // 524288

    build_table_kernel<<<16, 256>>>(weight);

    const int smem_bytes = (1024 + 2 * TILE_F4) * 16;   // 80 KB
    static int attr_done = 0;
    if (!attr_done) {
        cudaFuncSetAttribute(embed_kernel,
                             cudaFuncAttributeMaxDynamicSharedMemorySize,
                             smem_bytes);
        attr_done = 1;
    }

    int blocks = 296;                               // 2 per SM, balanced
    const int n_tiles = n_rows / TILE_ROWS;
    if (blocks > n_tiles && n_tiles > 0) blocks = n_tiles;
    if (n_tiles == 0) blocks = 1;

    cudaLaunchConfig_t cfg = {};
    cfg.gridDim  = dim3((unsigned)blocks, 1, 1);
    cfg.blockDim = dim3(256, 1, 1);
    cfg.dynamicSmemBytes = smem_bytes;
    cfg.stream = 0;
    cudaLaunchAttribute attr[1];
    attr[0].id = cudaLaunchAttributeProgrammaticStreamSerialization;
    attr[0].val.programmaticStreamSerializationAllowed = 1;
    cfg.attrs = attr;
    cfg.numAttrs = 1;

    cudaError_t e = cudaLaunchKernelEx(&cfg, embed_kernel, x, low, out, n_rows);
    if (e != cudaSuccess) {
        embed_kernel<<<blocks, 256, smem_bytes>>>(x, low, out, n_rows);
    }
}